// round 15
// baseline (speedup 1.0000x reference)
#include <cuda_runtime.h>
#include <cuda_bf16.h>

#define N_PTS 8192
#define D_TOK 384
#define KNN_K 16
#define KIN   387            // D_TOK + 3
#define KPAD  400            // padded K (multiple of 16)
#define KP2   (KPAD / 2)     // 200 k-pairs
#define NOUT  768            // [a | b] concatenated outputs
#define TILE  1024           // KNN candidate tile (points)
#define STAGES (KPAD / 16)   // 25 gemm k-stages

#define FLT_BIG 3.402823e38f

typedef unsigned long long u64;
typedef unsigned u32;

// ---------------- scratch (allocation-free rule: __device__ globals) --------
__device__ u32    g_AH[N_PTS * KP2];     // bf16x2-packed hi(X)  6.6 MB
__device__ u32    g_AL[N_PTS * KP2];     // bf16x2-packed lo(X)  6.6 MB
__device__ u32    g_BH[KP2 * NOUT];      // bf16x2-packed hi(W)  0.6 MB
__device__ u32    g_BL[KP2 * NOUT];      // bf16x2-packed lo(W)  0.6 MB
__device__ float  g_C [N_PTS * NOUT];    // 25.2 MB [a_i | b_i]
__device__ int    g_knn[N_PTS * KNN_K];
__device__ float4 g_P [N_PTS];           // {x, y, z, |p|^2}

// ---------------- bf16 / async helpers --------------------------------------
__device__ __forceinline__ u32 pack_hi_lo(float v0, float v1, bool lo)
{
    __nv_bfloat16 h0 = __float2bfloat16(v0);
    __nv_bfloat16 h1 = __float2bfloat16(v1);
    if (lo) {
        h0 = __float2bfloat16(v0 - __bfloat162float(h0));
        h1 = __float2bfloat16(v1 - __bfloat162float(h1));
    }
    __nv_bfloat162 p = __nv_bfloat162(h0, h1);   // x = low half (even k)
    return *reinterpret_cast<u32*>(&p);
}

__device__ __forceinline__ void mma_bf16(float* c, const u32* a, u32 b0, u32 b1)
{
    asm volatile(
        "mma.sync.aligned.m16n8k16.row.col.f32.bf16.bf16.f32 "
        "{%0,%1,%2,%3}, {%4,%5,%6,%7}, {%8,%9}, {%0,%1,%2,%3};\n"
        : "+f"(c[0]), "+f"(c[1]), "+f"(c[2]), "+f"(c[3])
        : "r"(a[0]), "r"(a[1]), "r"(a[2]), "r"(a[3]), "r"(b0), "r"(b1));
}

__device__ __forceinline__ void cp_async16(u32 smem_addr, const void* gptr)
{
    asm volatile("cp.async.cg.shared.global [%0], [%1], 16;"
        :: "r"(smem_addr), "l"(gptr));
}
__device__ __forceinline__ void cp_commit()  { asm volatile("cp.async.commit_group;"); }
__device__ __forceinline__ void cp_wait0()   { asm volatile("cp.async.wait_group 0;" ::: "memory"); }

// ---------------- pack kernels ---------------------------------------------
__global__ void pack_p(const float* __restrict__ xyz)
{
    int i = blockIdx.x * 256 + threadIdx.x;
    if (i < N_PTS) {
        float x = xyz[3 * i], y = xyz[3 * i + 1], z = xyz[3 * i + 2];
        g_P[i] = make_float4(x, y, z, x * x + y * y + z * z);
    }
}

__device__ __forceinline__ float xval(const float* token, const float* xyz, int i, int k)
{
    if (k < D_TOK) return token[i * D_TOK + k];
    if (k < KIN)   return xyz[i * 3 + (k - D_TOK)];
    return 0.f;
}

__global__ void pack_x(const float* __restrict__ token, const float* __restrict__ xyz)
{
    int i = blockIdx.x;
    for (int kp = threadIdx.x; kp < KP2; kp += blockDim.x) {
        float v0 = xval(token, xyz, i, 2 * kp);
        float v1 = xval(token, xyz, i, 2 * kp + 1);
        g_AH[i * KP2 + kp] = pack_hi_lo(v0, v1, false);
        g_AL[i * KP2 + kp] = pack_hi_lo(v0, v1, true);
    }
}

__device__ __forceinline__ float wval(const float* W1, int k, int n)
{
    if (k >= KIN) return 0.f;
    if (n < D_TOK) return W1[k * D_TOK + n];
    return W1[(KIN + k) * D_TOK + (n - D_TOK)];
}

__global__ void pack_w(const float* __restrict__ W1)
{
    int kp = blockIdx.x;              // 0..KP2-1
    for (int n = threadIdx.x; n < NOUT; n += blockDim.x) {
        float v0 = wval(W1, 2 * kp, n);
        float v1 = wval(W1, 2 * kp + 1, n);
        g_BH[kp * NOUT + n] = pack_hi_lo(v0, v1, false);
        g_BL[kp * NOUT + n] = pack_hi_lo(v0, v1, true);
    }
}

// ---------------- KNN: warp-per-query, distributed sorted top-16 ------------
// R8-proven version (104us): 1 candidate/lane fast path, ballot-gated
// warp-collective shift-insert, exact u64 key gate, sentinel decode guarded.
__global__ __launch_bounds__(256) void knn_warp()
{
    __shared__ float4 sP[TILE];     // 16 KB
    int lane = threadIdx.x & 31;
    int wid  = threadIdx.x >> 5;
    int q    = blockIdx.x * 8 + wid;

    float4 Q = g_P[q];
    float sqi = Q.w;
    float nx = -2.f * Q.x, ny = -2.f * Q.y, nz = -2.f * Q.z;

    u64   mykey = ~0ull;     // lanes 0..15: sorted list; others unused
    u64   Tkey  = ~0ull;     // key of current 16th-best (lane 15), broadcast
    float Td    = FLT_BIG;

    for (int t0 = 0; t0 < N_PTS; t0 += TILE) {
        __syncthreads();
        #pragma unroll
        for (int i = 0; i < TILE / 256; i++)
            sP[threadIdx.x + 256 * i] = g_P[t0 + threadIdx.x + 256 * i];
        __syncthreads();

        #pragma unroll 4
        for (int s = 0; s < TILE / 32; s++) {
            float4 c = sP[s * 32 + lane];
            float d = sqi + c.w;
            d = fmaf(nx, c.x, d);
            d = fmaf(ny, c.y, d);
            d = fmaf(nz, c.z, d);
            unsigned bal = __ballot_sync(0xFFFFFFFFu, d <= Td);
            while (bal) {                        // uniform across warp
                int src = __ffs(bal) - 1;
                bal &= bal - 1;
                float dd = __shfl_sync(0xFFFFFFFFu, d, src);
                int jj = t0 + s * 32 + src;
                if (jj != q) {
                    unsigned b = __float_as_uint(dd);
                    unsigned m = b ^ (unsigned)(((int)b >> 31) | 0x80000000);
                    u64 k = ((u64)m << 32) | (unsigned)jj;
                    if (k < Tkey) {
                        bool less = mykey > k;
                        unsigned ib = __ballot_sync(0xFFFFFFFFu, less) & 0xFFFFu;
                        int pos = 16 - __popc(ib);
                        u64 up = __shfl_up_sync(0xFFFFFFFFu, mykey, 1);
                        if (lane < 16 && less)
                            mykey = (lane == pos) ? k : up;
                        Tkey = __shfl_sync(0xFFFFFFFFu, mykey, 15);
                        unsigned hb = (unsigned)(Tkey >> 32);
                        unsigned fb = (hb & 0x80000000u) ? (hb ^ 0x80000000u) : ~hb;
                        Td = (hb == 0xFFFFFFFFu) ? FLT_BIG : __uint_as_float(fb);
                    }
                }
            }
        }
    }
    if (lane < KNN_K)
        g_knn[q * KNN_K + lane] = (int)(unsigned)(mykey & 0xFFFFFFFFull);
}

// ---------------- node GEMM via bf16 tensor cores (3-MMA split) -------------
// R9 128x128 shape, but stage loads via cp.async (no register staging):
// frees ~48 regs -> 3 blocks/SM under launch_bounds(256,3), and removes the
// LDG long-scoreboard stalls from the issue stream.
__global__ __launch_bounds__(256, 3) void gemm_kernel(const float* __restrict__ b1)
{
    __shared__ u32 Ah[2][128][12];   // [buf][m][kpair], pitch 12 (conflict-free)
    __shared__ u32 Al[2][128][12];
    __shared__ u32 Bh[2][8][136];    // [buf][kpair][n],  pitch 136 (conflict-free)
    __shared__ u32 Bl[2][8][136];

    int tid = threadIdx.x;
    int bm = blockIdx.y, bn = blockIdx.x;
    int wid = tid >> 5, lane = tid & 31;
    int wm = wid & 3, wn = wid >> 2;            // warp tile (wm*32, wn*64)
    int g = lane >> 2, t = lane & 3;

    int arow = tid >> 1, ah4 = (tid & 1) << 2;  // A: 128 rows x 8 u32
    int brow = tid >> 5, bc4 = (tid & 31) << 2; // B: 8 rows x 128 u32

    const u32* Agh = g_AH + (bm * 128 + arow) * KP2 + ah4;
    const u32* Agl = g_AL + (bm * 128 + arow) * KP2 + ah4;
    const u32* Bgh = g_BH + brow * NOUT + bn * 128 + bc4;
    const u32* Bgl = g_BL + brow * NOUT + bn * 128 + bc4;

    // smem byte addresses for this thread's cp.async destinations
    u32 sAh = (u32)__cvta_generic_to_shared(&Ah[0][arow][ah4]);
    u32 sAl = (u32)__cvta_generic_to_shared(&Al[0][arow][ah4]);
    u32 sBh = (u32)__cvta_generic_to_shared(&Bh[0][brow][bc4]);
    u32 sBl = (u32)__cvta_generic_to_shared(&Bl[0][brow][bc4]);
    const u32 strA = 128 * 12 * 4;   // bytes between A buffers
    const u32 strB = 8 * 136 * 4;    // bytes between B buffers

    float acc[2][8][4];
    #pragma unroll
    for (int i = 0; i < 2; i++)
        #pragma unroll
        for (int j = 0; j < 8; j++)
            #pragma unroll
            for (int r = 0; r < 4; r++) acc[i][j][r] = 0.f;

    // stage 0 via cp.async
    cp_async16(sAh, Agh);
    cp_async16(sAl, Agl);
    cp_async16(sBh, Bgh);
    cp_async16(sBl, Bgl);
    cp_commit();
    cp_wait0();
    __syncthreads();

    for (int s = 0; s < STAGES; s++) {
        int cur = s & 1;
        if (s + 1 < STAGES) {
            int nxt = cur ^ 1;
            int kp = (s + 1) * 8;
            cp_async16(sAh + nxt * strA, Agh + kp);
            cp_async16(sAl + nxt * strA, Agl + kp);
            cp_async16(sBh + nxt * strB, Bgh + kp * NOUT);
            cp_async16(sBl + nxt * strB, Bgl + kp * NOUT);
            cp_commit();
        }

        // ---- compute on cur (R9-proven fragment pattern) ----
        u32 fah[2][4], fal[2][4];
        #pragma unroll
        for (int mt = 0; mt < 2; mt++) {
            int r = wm * 32 + mt * 16 + g;
            fah[mt][0] = Ah[cur][r][t];
            fah[mt][1] = Ah[cur][r + 8][t];
            fah[mt][2] = Ah[cur][r][t + 4];
            fah[mt][3] = Ah[cur][r + 8][t + 4];
            fal[mt][0] = Al[cur][r][t];
            fal[mt][1] = Al[cur][r + 8][t];
            fal[mt][2] = Al[cur][r][t + 4];
            fal[mt][3] = Al[cur][r + 8][t + 4];
        }
        #pragma unroll
        for (int nt = 0; nt < 8; nt++) {
            int cn = wn * 64 + nt * 8 + g;
            u32 bh0 = Bh[cur][t][cn],     bh1 = Bh[cur][t + 4][cn];
            u32 bl0 = Bl[cur][t][cn],     bl1 = Bl[cur][t + 4][cn];
            #pragma unroll
            for (int mt = 0; mt < 2; mt++) {
                mma_bf16(acc[mt][nt], fah[mt], bh0, bh1);
                mma_bf16(acc[mt][nt], fah[mt], bl0, bl1);
                mma_bf16(acc[mt][nt], fal[mt], bh0, bh1);
            }
        }

        if (s + 1 < STAGES) cp_wait0();
        __syncthreads();
    }

    // epilogue
    bool hasB = (bn < 3);
    #pragma unroll
    for (int mt = 0; mt < 2; mt++) {
        int row0 = bm * 128 + wm * 32 + mt * 16 + g;
        #pragma unroll
        for (int nt = 0; nt < 8; nt++) {
            int col = bn * 128 + wn * 64 + nt * 8 + 2 * t;
            float bias0 = hasB ? b1[col]     : 0.f;
            float bias1 = hasB ? b1[col + 1] : 0.f;
            float2 v0 = make_float2(acc[mt][nt][0] + bias0, acc[mt][nt][1] + bias1);
            float2 v1 = make_float2(acc[mt][nt][2] + bias0, acc[mt][nt][3] + bias1);
            *(float2*)&g_C[row0 * NOUT + col]       = v0;
            *(float2*)&g_C[(row0 + 8) * NOUT + col] = v1;
        }
    }
}

// ---------------- edge kernel: one warp per node ----------------------------
__global__ __launch_bounds__(256) void edge_kernel(const float* __restrict__ xyz,
                                                   const float* __restrict__ W2,
                                                   const float* __restrict__ b2,
                                                   float* __restrict__ out)
{
    int gwarp = (blockIdx.x * blockDim.x + threadIdx.x) >> 5;
    int lane  = threadIdx.x & 31;
    if (gwarp >= N_PTS) return;

    const float* Ci = g_C + gwarp * NOUT;

    float4 s[3];
    float w2[12][3];
    #pragma unroll
    for (int dn = 0; dn < 3; dn++) {
        int dim0 = lane * 4 + dn * 128;
        float4 a = *(const float4*)(Ci + dim0);           // a_i (has b1)
        float4 b = *(const float4*)(Ci + D_TOK + dim0);   // b_i
        s[dn] = make_float4(a.x - b.x, a.y - b.y, a.z - b.z, a.w - b.w);
        #pragma unroll
        for (int u = 0; u < 4; u++)
            #pragma unroll
            for (int c = 0; c < 3; c++)
                w2[dn * 4 + u][c] = W2[(dim0 + u) * 3 + c];
    }

    float acc0 = 0.f, acc1 = 0.f, acc2 = 0.f;
    #pragma unroll 4
    for (int j = 0; j < KNN_K; j++) {
        int nj = g_knn[gwarp * KNN_K + j];
        const float* Bj = g_C + nj * NOUT + D_TOK;
        #pragma unroll
        for (int dn = 0; dn < 3; dn++) {
            float4 b = *(const float4*)(Bj + lane * 4 + dn * 128);
            float h;
            h = fmaxf(s[dn].x + b.x, 0.f);
            acc0 = fmaf(h, w2[dn*4+0][0], acc0); acc1 = fmaf(h, w2[dn*4+0][1], acc1); acc2 = fmaf(h, w2[dn*4+0][2], acc2);
            h = fmaxf(s[dn].y + b.y, 0.f);
            acc0 = fmaf(h, w2[dn*4+1][0], acc0); acc1 = fmaf(h, w2[dn*4+1][1], acc1); acc2 = fmaf(h, w2[dn*4+1][2], acc2);
            h = fmaxf(s[dn].z + b.z, 0.f);
            acc0 = fmaf(h, w2[dn*4+2][0], acc0); acc1 = fmaf(h, w2[dn*4+2][1], acc1); acc2 = fmaf(h, w2[dn*4+2][2], acc2);
            h = fmaxf(s[dn].w + b.w, 0.f);
            acc0 = fmaf(h, w2[dn*4+3][0], acc0); acc1 = fmaf(h, w2[dn*4+3][1], acc1); acc2 = fmaf(h, w2[dn*4+3][2], acc2);
        }
    }

    #pragma unroll
    for (int off = 16; off > 0; off >>= 1) {
        acc0 += __shfl_down_sync(0xFFFFFFFFu, acc0, off);
        acc1 += __shfl_down_sync(0xFFFFFFFFu, acc1, off);
        acc2 += __shfl_down_sync(0xFFFFFFFFu, acc2, off);
    }

    if (lane == 0) {
        const float inv = 1.f / 16.f;
        out[gwarp * 3 + 0] = xyz[gwarp * 3 + 0] + acc0 * inv + b2[0];
        out[gwarp * 3 + 1] = xyz[gwarp * 3 + 1] + acc1 * inv + b2[1];
        out[gwarp * 3 + 2] = xyz[gwarp * 3 + 2] + acc2 * inv + b2[2];
    }
}

// ---------------- launch ----------------------------------------------------
// gemm at launch index 3 (the captured one) to verify the cp.async/occupancy
// prediction directly.
extern "C" void kernel_launch(void* const* d_in, const int* in_sizes, int n_in,
                              void* d_out, int out_size)
{
    const float* xyz   = (const float*)d_in[0];
    const float* token = (const float*)d_in[1];
    const float* W1    = (const float*)d_in[2];
    const float* b1    = (const float*)d_in[3];
    const float* W2    = (const float*)d_in[4];
    const float* b2    = (const float*)d_in[5];
    float* out = (float*)d_out;

    pack_p<<<N_PTS / 256, 256>>>(xyz);
    pack_x<<<N_PTS, 128>>>(token, xyz);
    pack_w<<<KP2, 256>>>(W1);
    gemm_kernel<<<dim3(NOUT / 128, N_PTS / 128), 256>>>(b1);
    knn_warp<<<N_PTS / 8, 256>>>();
    edge_kernel<<<N_PTS / 8, 256>>>(xyz, W2, b2, out);
}